// round 12
// baseline (speedup 1.0000x reference)
#include <cuda_runtime.h>
#include <cuda_fp16.h>
#include <cstdint>
#include <cstddef>

#define DEV_INLINE __device__ __forceinline__

// ============================ problem sizes =============================
static constexpr int BB    = 8192;
static constexpr int TT    = 10;
static constexpr int DD    = 1024;
static constexpr int M_ALL = BB * TT;     // 81920
static constexpr int N_ALL = 3 * DD;      // 3072 (q|k|v)
static constexpr int K_ALL = DD;          // 1024
static constexpr int TM    = 128;
static constexpr int TN    = 128;
static constexpr int KC    = 64;          // K elems per chunk (128B fp16 rows)
static constexpr int NCHUNK = K_ALL / KC; // 16
static constexpr float EPSV = 1e-5f;

// ============================ device scratch ============================
__device__ __half g_x_hi[(size_t)M_ALL * DD];
__device__ __half g_x_lo[(size_t)M_ALL * DD];
__device__ __half g_w[(size_t)N_ALL * DD];
__device__ float  g_bias[N_ALL];
__device__ float  g_qkv[(size_t)M_ALL * N_ALL];  // relu(x@W^T + b)

// ============================ PTX helpers ===============================
DEV_INLINE uint32_t smem_to_u32(const void* p) {
    uint32_t a;
    asm("{ .reg .u64 t; cvta.to.shared.u64 t, %1; cvt.u32.u64 %0, t; }"
        : "=r"(a) : "l"(p));
    return a;
}

#define CP_ASYNC16(dst, src) \
    asm volatile("cp.async.cg.shared.global [%0], [%1], 16;\n" :: "r"(dst), "l"(src))
#define CP_ASYNC_COMMIT() asm volatile("cp.async.commit_group;\n" ::: "memory")

DEV_INLINE void ldmatrix_x4(uint32_t* r, uint32_t addr) {
    asm volatile("ldmatrix.sync.aligned.m8n8.x4.shared.b16 {%0,%1,%2,%3}, [%4];"
                 : "=r"(r[0]), "=r"(r[1]), "=r"(r[2]), "=r"(r[3]) : "r"(addr));
}

DEV_INLINE void mma_f16(float* d, const uint32_t* a, uint32_t b0, uint32_t b1) {
    asm volatile(
        "mma.sync.aligned.m16n8k16.row.col.f32.f16.f16.f32 "
        "{%0,%1,%2,%3}, {%4,%5,%6,%7}, {%8,%9}, {%0,%1,%2,%3};"
        : "+f"(d[0]), "+f"(d[1]), "+f"(d[2]), "+f"(d[3])
        : "r"(a[0]), "r"(a[1]), "r"(a[2]), "r"(a[3]), "r"(b0), "r"(b1));
}

DEV_INLINE uint32_t sw128(uint32_t off) { return off ^ ((off >> 3) & 0x70); }

// ============================ prep kernels ==============================
// x = x_in + pe; hi = fp16(x), lo = fp16(x - hi). One float4 per thread.
__global__ void prep_x_kernel(const float* __restrict__ x,
                              const float* __restrict__ pe) {
    size_t i4  = (size_t)blockIdx.x * blockDim.x + threadIdx.x;  // 20,971,520
    size_t idx = i4 * 4;
    int d = (int)(idx & (DD - 1));
    int t = (int)((idx >> 10) % TT);
    float4 xv = *(const float4*)(x + idx);
    float4 pv = *(const float4*)(pe + (size_t)t * DD + d);
    float v0 = xv.x + pv.x, v1 = xv.y + pv.y, v2 = xv.z + pv.z, v3 = xv.w + pv.w;
    __half h0 = __float2half_rn(v0), h1 = __float2half_rn(v1);
    __half h2 = __float2half_rn(v2), h3 = __float2half_rn(v3);
    __half l0 = __float2half_rn(v0 - __half2float(h0));
    __half l1 = __float2half_rn(v1 - __half2float(h1));
    __half l2 = __float2half_rn(v2 - __half2float(h2));
    __half l3 = __float2half_rn(v3 - __half2float(h3));
    *(__half2*)(g_x_hi + idx)     = __halves2half2(h0, h1);
    *(__half2*)(g_x_hi + idx + 2) = __halves2half2(h2, h3);
    *(__half2*)(g_x_lo + idx)     = __halves2half2(l0, l1);
    *(__half2*)(g_x_lo + idx + 2) = __halves2half2(l2, l3);
}

// W: combined [3072,1024] K-major rows = [Wq; Wk; Wv] in fp16, plus bias.
__global__ void prep_w_kernel(const float* __restrict__ Wq, const float* __restrict__ Wk,
                              const float* __restrict__ Wv, const float* __restrict__ bq,
                              const float* __restrict__ bk, const float* __restrict__ bv) {
    size_t i4  = (size_t)blockIdx.x * blockDim.x + threadIdx.x;  // 786,432
    size_t idx = i4 * 4;
    int n = (int)(idx >> 10);
    int d = (int)(idx & (DD - 1));
    const float* W;
    int r;
    if (n < DD)          { W = Wq; r = n; }
    else if (n < 2 * DD) { W = Wk; r = n - DD; }
    else                 { W = Wv; r = n - 2 * DD; }
    float4 wv = *(const float4*)(W + (size_t)r * DD + d);
    *(__half2*)(g_w + idx)     = __halves2half2(__float2half_rn(wv.x), __float2half_rn(wv.y));
    *(__half2*)(g_w + idx + 2) = __halves2half2(__float2half_rn(wv.z), __float2half_rn(wv.w));
    if (i4 < (size_t)N_ALL) {
        int nn = (int)i4;
        float b = (nn < DD) ? bq[nn] : (nn < 2 * DD) ? bk[nn - DD] : bv[nn - 2 * DD];
        g_bias[nn] = b;
    }
}

// ============================ GEMM kernel ===============================
// qkv[m,n] = relu( sum_k x[m,k]*W[n,k] + bias[n] )
// 2-term fp16 split: acc += x_hi.W + x_lo.W (B fragments shared by both terms).
// mma.sync m16n8k16 f16/f32, cp.async 2-stage pipeline, SW128 swizzle.
// Stage: A_hi 16KB + A_lo 16KB + B 16KB = 48KB; 2 stages = 96KB. occ 2.
// Grid: x = N tiles (24, fastest) so a wave's A working set stays L2-resident.
__global__ void __launch_bounds__(256, 2) qkv_gemm_kernel() {
    extern __shared__ __align__(1024) char smem[];
    const uint32_t sbase = smem_to_u32(smem);
    const int tid  = threadIdx.x;
    const int wid  = tid >> 5;
    const int lane = tid & 31;
    const int n0 = blockIdx.x * TN;       // N fastest
    const int m0 = blockIdx.y * TM;
    const int warp_m = (wid & 3) * 32;    // 4 warps along M
    const int warp_n = (wid >> 2) * 64;   // 2 warps along N

    auto load_chunk = [&](int c) {
        const uint32_t stb = sbase + (uint32_t)(c & 1) * 49152u;
        const size_t k0 = (size_t)c * KC;
        #pragma unroll
        for (int l = 0; l < 12; l++) {
            int i   = tid + l * 256;      // 0..3071
            int arr = i >> 10;            // 0 = A_hi, 1 = A_lo, 2 = B
            int w   = i & 1023;
            int r   = w >> 3;             // row 0..127
            int j   = w & 7;              // 16B piece
            uint32_t dst = stb + (uint32_t)arr * 16384u
                         + sw128((uint32_t)(r * 128 + j * 16));
            const __half* src =
                (arr == 0) ? g_x_hi + ((size_t)(m0 + r) * K_ALL + k0 + j * 8)
              : (arr == 1) ? g_x_lo + ((size_t)(m0 + r) * K_ALL + k0 + j * 8)
              :              g_w    + ((size_t)(n0 + r) * K_ALL + k0 + j * 8);
            CP_ASYNC16(dst, src);
        }
        CP_ASYNC_COMMIT();
    };

    load_chunk(0);
    load_chunk(1);

    float acc[2][8][4];
    #pragma unroll
    for (int i = 0; i < 2; i++)
        #pragma unroll
        for (int j = 0; j < 8; j++)
            #pragma unroll
            for (int e = 0; e < 4; e++) acc[i][j][e] = 0.f;

    const int colb_lane = ((lane >> 4) << 4);
    const int row_lane  = (lane & 15);

    for (int c = 0; c < NCHUNK; c++) {
        if (c == NCHUNK - 1) asm volatile("cp.async.wait_group 0;\n" ::: "memory");
        else                 asm volatile("cp.async.wait_group 1;\n" ::: "memory");
        __syncthreads();

        const uint32_t sAh = sbase + (uint32_t)(c & 1) * 49152u;
        const uint32_t sAl = sAh + 16384u;
        const uint32_t sB  = sAh + 32768u;
        #pragma unroll
        for (int ks = 0; ks < 4; ks++) {
            const int colb = ks * 32 + colb_lane;
            uint32_t b[4][4], ah[2][4], al[2][4];
            #pragma unroll
            for (int t = 0; t < 4; t++) {
                uint32_t off = (uint32_t)((warp_n + 16 * t + row_lane) * 128 + colb);
                ldmatrix_x4(b[t], sB + sw128(off));
            }
            #pragma unroll
            for (int i = 0; i < 2; i++) {
                uint32_t off = (uint32_t)((warp_m + 16 * i + row_lane) * 128 + colb);
                ldmatrix_x4(ah[i], sAh + sw128(off));
            }
            #pragma unroll
            for (int i = 0; i < 2; i++) {
                uint32_t off = (uint32_t)((warp_m + 16 * i + row_lane) * 128 + colb);
                ldmatrix_x4(al[i], sAl + sw128(off));
            }
            #pragma unroll
            for (int i = 0; i < 2; i++)
                #pragma unroll
                for (int t = 0; t < 4; t++) {
                    mma_f16(acc[i][2 * t],     ah[i], b[t][0], b[t][2]);
                    mma_f16(acc[i][2 * t + 1], ah[i], b[t][1], b[t][3]);
                    mma_f16(acc[i][2 * t],     al[i], b[t][0], b[t][2]);
                    mma_f16(acc[i][2 * t + 1], al[i], b[t][1], b[t][3]);
                }
        }
        __syncthreads();                     // all warps done with stage c&1
        if (c + 2 < NCHUNK) load_chunk(c + 2);
    }

    // Epilogue: bias + relu, direct to g_qkv.
    const int rr = lane >> 2;
    const int cc = (lane & 3) * 2;
    #pragma unroll
    for (int i = 0; i < 2; i++) {
        const int gm = m0 + warp_m + 16 * i + rr;
        #pragma unroll
        for (int j = 0; j < 8; j++) {
            const int gn = n0 + warp_n + 8 * j + cc;
            const float b0 = g_bias[gn], b1 = g_bias[gn + 1];
            float2 o0, o1;
            o0.x = fmaxf(acc[i][j][0] + b0, 0.f);
            o0.y = fmaxf(acc[i][j][1] + b1, 0.f);
            o1.x = fmaxf(acc[i][j][2] + b0, 0.f);
            o1.y = fmaxf(acc[i][j][3] + b1, 0.f);
            *(float2*)(g_qkv + (size_t)gm * N_ALL + gn)       = o0;
            *(float2*)(g_qkv + (size_t)(gm + 8) * N_ALL + gn) = o1;
        }
    }
}

// ====================== attention + residual + LN =======================
// One CTA (256 threads) per batch row b. Single 40KB k/v buffer; q and x
// streamed from global as float4 per thread. smem ~41KB -> 5 CTAs/SM.
__global__ void __launch_bounds__(256) attn_kernel(
    const float* __restrict__ x_in, const float* __restrict__ pe,
    const float* __restrict__ gamma, const float* __restrict__ beta,
    float* __restrict__ out_x, float* __restrict__ out_attn, int write_attn) {
    extern __shared__ __align__(16) char smem_raw[];
    float* kv     = (float*)smem_raw;    // 10 x 1024
    float* logits = kv + 10240;          // 100 (pad 104)
    float* red    = logits + 104;        // 88

    const int tid = threadIdx.x, wid = tid >> 5, lid = tid & 31;
    const size_t b = blockIdx.x;
    const float* qkv_b = g_qkv + b * (size_t)TT * N_ALL;
    const int d0 = tid * 4;

    // Stage k
    for (int i = tid; i < 2560; i += 256) {
        int t = i >> 8, c = (i & 255) * 4;
        *(float4*)(kv + t * DD + c) =
            *(const float4*)(qkv_b + (size_t)t * N_ALL + DD + c);
    }
    __syncthreads();

    // logits[t][s] = (q[t] . k[s]) / sqrt(D); q streamed.
    const float scale = rsqrtf((float)DD);
    for (int t = 0; t < TT; t++) {
        float4 q4 = *(const float4*)(qkv_b + (size_t)t * N_ALL + d0);
        float part[TT];
        #pragma unroll
        for (int s = 0; s < TT; s++) {
            float4 k4 = *(const float4*)(kv + s * DD + d0);
            part[s] = q4.x * k4.x + q4.y * k4.y + q4.z * k4.z + q4.w * k4.w;
        }
        #pragma unroll
        for (int o = 16; o; o >>= 1)
            #pragma unroll
            for (int s = 0; s < TT; s++)
                part[s] += __shfl_xor_sync(0xFFFFFFFFu, part[s], o);
        if (lid == 0)
            #pragma unroll
            for (int s = 0; s < TT; s++) red[wid * TT + s] = part[s];
        __syncthreads();
        if (tid < TT) {
            float a2 = 0.f;
            #pragma unroll
            for (int w = 0; w < 8; w++) a2 += red[w * TT + tid];
            logits[t * TT + tid] = a2 * scale;
        }
        __syncthreads();
    }

    // Softmax rows (threads 0..9), write attn output.
    if (tid < TT) {
        float m = -1e30f;
        #pragma unroll
        for (int s = 0; s < TT; s++) m = fmaxf(m, logits[tid * TT + s]);
        float e[TT], sum = 0.f;
        #pragma unroll
        for (int s = 0; s < TT; s++) { e[s] = expf(logits[tid * TT + s] - m); sum += e[s]; }
        float inv = 1.f / sum;
        #pragma unroll
        for (int s = 0; s < TT; s++) {
            float a = e[s] * inv;
            logits[tid * TT + s] = a;
            if (write_attn) out_attn[(b * TT + tid) * TT + s] = a;
        }
    }
    __syncthreads();

    // Stage v (overwrite kv)
    for (int i = tid; i < 2560; i += 256) {
        int t = i >> 8, c = (i & 255) * 4;
        *(float4*)(kv + t * DD + c) =
            *(const float4*)(qkv_b + (size_t)t * N_ALL + 2 * DD + c);
    }
    __syncthreads();

    // out = attn @ v; residual (x streamed); LayerNorm; coalesced store.
    const float4 g4 = *(const float4*)(gamma + d0);
    const float4 be4 = *(const float4*)(beta + d0);
    for (int t = 0; t < TT; t++) {
        float a[TT];
        #pragma unroll
        for (int s = 0; s < TT; s++) a[s] = logits[t * TT + s];
        float4 xv = *(const float4*)(x_in + (b * TT + t) * (size_t)DD + d0);
        float4 pv = *(const float4*)(pe + (size_t)t * DD + d0);
        xv.x += pv.x; xv.y += pv.y; xv.z += pv.z; xv.w += pv.w;
        float4 o = make_float4(0.f, 0.f, 0.f, 0.f);
        #pragma unroll
        for (int s = 0; s < TT; s++) {
            float4 v4 = *(const float4*)(kv + s * DD + d0);
            o.x += a[s] * v4.x; o.y += a[s] * v4.y;
            o.z += a[s] * v4.z; o.w += a[s] * v4.w;
        }
        float4 v;
        v.x = xv.x + o.x; v.y = xv.y + o.y; v.z = xv.z + o.z; v.w = xv.w + o.w;
        float s1 = v.x + v.y + v.z + v.w;
        float s2 = v.x * v.x + v.y * v.y + v.z * v.z + v.w * v.w;
        #pragma unroll
        for (int of = 16; of; of >>= 1) {
            s1 += __shfl_xor_sync(0xFFFFFFFFu, s1, of);
            s2 += __shfl_xor_sync(0xFFFFFFFFu, s2, of);
        }
        if (lid == 0) { red[wid] = s1; red[8 + wid] = s2; }
        __syncthreads();
        if (tid == 0) {
            float ts1 = 0.f, ts2 = 0.f;
            #pragma unroll
            for (int w = 0; w < 8; w++) { ts1 += red[w]; ts2 += red[8 + w]; }
            float mu  = ts1 * (1.f / DD);
            float var = ts2 * (1.f / DD) - mu * mu;
            red[16] = mu;
            red[17] = rsqrtf(var + EPSV);
        }
        __syncthreads();
        float mu = red[16], rstd = red[17];
        float4 r;
        r.x = (v.x - mu) * rstd * g4.x + be4.x;
        r.y = (v.y - mu) * rstd * g4.y + be4.y;
        r.z = (v.z - mu) * rstd * g4.z + be4.z;
        r.w = (v.w - mu) * rstd * g4.w + be4.w;
        *(float4*)(out_x + (b * TT + t) * (size_t)DD + d0) = r;
        __syncthreads();  // protect red[] reuse next iteration
    }
}

// ============================ launch ====================================
extern "C" void kernel_launch(void* const* d_in, const int* in_sizes, int n_in,
                              void* d_out, int out_size) {
    const float* x     = (const float*)d_in[0];
    const float* pe    = (const float*)d_in[1];
    const float* Wq    = (const float*)d_in[2];
    const float* bq    = (const float*)d_in[3];
    const float* Wk    = (const float*)d_in[4];
    const float* bk    = (const float*)d_in[5];
    const float* Wv    = (const float*)d_in[6];
    const float* bv    = (const float*)d_in[7];
    const float* gamma = (const float*)d_in[8];
    const float* beta  = (const float*)d_in[9];
    float* out = (float*)d_out;

    (void)in_sizes; (void)n_in;

    cudaFuncSetAttribute(qkv_gemm_kernel,
                         cudaFuncAttributeMaxDynamicSharedMemorySize, 98304);
    cudaFuncSetAttribute(attn_kernel,
                         cudaFuncAttributeMaxDynamicSharedMemorySize, 41728);

    // 1) split x+pe into fp16 hi/lo; W -> fp16
    prep_x_kernel<<<81920, 256>>>(x, pe);
    prep_w_kernel<<<3072, 256>>>(Wq, Wk, Wv, bq, bk, bv);

    // 2) qkv = relu(x @ [Wq;Wk;Wv]^T + b), 2-term fp16 split mma.sync
    dim3 ggrid(N_ALL / TN, M_ALL / TM);   // (24, 640) — N fastest for L2 reuse
    qkv_gemm_kernel<<<ggrid, 256, 98304>>>();

    // 3) attention + softmax + residual + LN (+ attn matrix output)
    long long need = (long long)M_ALL * DD + (long long)BB * TT * TT;
    int write_attn = ((long long)out_size >= need) ? 1 : 0;
    attn_kernel<<<BB, 256, 41728>>>(x, pe, gamma, beta,
                                    out, out + (size_t)M_ALL * DD, write_attn);
}

// round 14
// speedup vs baseline: 1.6358x; 1.6358x over previous
#include <cuda_runtime.h>
#include <cuda_fp16.h>
#include <cstdint>
#include <cstddef>

#define DEV_INLINE __device__ __forceinline__

// ============================ problem sizes =============================
static constexpr int BB    = 8192;
static constexpr int TT    = 10;
static constexpr int DD    = 1024;
static constexpr int M_ALL = BB * TT;     // 81920
static constexpr int N_ALL = 3 * DD;      // 3072 (q|k|v)
static constexpr int K_ALL = DD;          // 1024
static constexpr int TM    = 128;
static constexpr int TN    = 128;
static constexpr int KC    = 64;          // K elems per chunk (128B fp16 rows)
static constexpr int NCHUNK = K_ALL / KC; // 16
static constexpr int STAGES = 3;
static constexpr float EPSV = 1e-5f;

// ============================ device scratch ============================
__device__ __half g_x[(size_t)M_ALL * DD];
__device__ __half g_w[(size_t)N_ALL * DD];
__device__ float  g_bias[N_ALL];
__device__ float  g_qkv[(size_t)M_ALL * N_ALL];  // relu(x@W^T + b)

// ============================ PTX helpers ===============================
DEV_INLINE uint32_t smem_to_u32(const void* p) {
    uint32_t a;
    asm("{ .reg .u64 t; cvta.to.shared.u64 t, %1; cvt.u32.u64 %0, t; }"
        : "=r"(a) : "l"(p));
    return a;
}

#define CP_ASYNC16(dst, src) \
    asm volatile("cp.async.cg.shared.global [%0], [%1], 16;\n" :: "r"(dst), "l"(src))
#define CP_ASYNC_COMMIT() asm volatile("cp.async.commit_group;\n" ::: "memory")

DEV_INLINE void ldmatrix_x4(uint32_t* r, uint32_t addr) {
    asm volatile("ldmatrix.sync.aligned.m8n8.x4.shared.b16 {%0,%1,%2,%3}, [%4];"
                 : "=r"(r[0]), "=r"(r[1]), "=r"(r[2]), "=r"(r[3]) : "r"(addr));
}

DEV_INLINE void mma_f16(float* d, const uint32_t* a, uint32_t b0, uint32_t b1) {
    asm volatile(
        "mma.sync.aligned.m16n8k16.row.col.f32.f16.f16.f32 "
        "{%0,%1,%2,%3}, {%4,%5,%6,%7}, {%8,%9}, {%0,%1,%2,%3};"
        : "+f"(d[0]), "+f"(d[1]), "+f"(d[2]), "+f"(d[3])
        : "r"(a[0]), "r"(a[1]), "r"(a[2]), "r"(a[3]), "r"(b0), "r"(b1));
}

DEV_INLINE uint32_t sw128(uint32_t off) { return off ^ ((off >> 3) & 0x70); }

// ============================ prep kernels ==============================
// x = fp16(x_in + pe). One float4 per thread.
__global__ void prep_x_kernel(const float* __restrict__ x,
                              const float* __restrict__ pe) {
    size_t i4  = (size_t)blockIdx.x * blockDim.x + threadIdx.x;  // 20,971,520
    size_t idx = i4 * 4;
    int d = (int)(idx & (DD - 1));
    int t = (int)((idx >> 10) % TT);
    float4 xv = *(const float4*)(x + idx);
    float4 pv = *(const float4*)(pe + (size_t)t * DD + d);
    *(__half2*)(g_x + idx) =
        __halves2half2(__float2half_rn(xv.x + pv.x), __float2half_rn(xv.y + pv.y));
    *(__half2*)(g_x + idx + 2) =
        __halves2half2(__float2half_rn(xv.z + pv.z), __float2half_rn(xv.w + pv.w));
}

// W: combined [3072,1024] K-major rows = [Wq; Wk; Wv] in fp16, plus bias.
__global__ void prep_w_kernel(const float* __restrict__ Wq, const float* __restrict__ Wk,
                              const float* __restrict__ Wv, const float* __restrict__ bq,
                              const float* __restrict__ bk, const float* __restrict__ bv) {
    size_t i4  = (size_t)blockIdx.x * blockDim.x + threadIdx.x;  // 786,432
    size_t idx = i4 * 4;
    int n = (int)(idx >> 10);
    int d = (int)(idx & (DD - 1));
    const float* W;
    int r;
    if (n < DD)          { W = Wq; r = n; }
    else if (n < 2 * DD) { W = Wk; r = n - DD; }
    else                 { W = Wv; r = n - 2 * DD; }
    float4 wv = *(const float4*)(W + (size_t)r * DD + d);
    *(__half2*)(g_w + idx)     = __halves2half2(__float2half_rn(wv.x), __float2half_rn(wv.y));
    *(__half2*)(g_w + idx + 2) = __halves2half2(__float2half_rn(wv.z), __float2half_rn(wv.w));
    if (i4 < (size_t)N_ALL) {
        int nn = (int)i4;
        float b = (nn < DD) ? bq[nn] : (nn < 2 * DD) ? bk[nn - DD] : bv[nn - 2 * DD];
        g_bias[nn] = b;
    }
}

// ============================ GEMM kernel ===============================
// qkv[m,n] = relu( sum_k x[m,k]*W[n,k] + bias[n] ), single-term fp16 mma.sync,
// 3-stage cp.async pipeline, SW128 swizzle. Stage = A 16KB + B 16KB = 32KB.
__global__ void __launch_bounds__(256, 2) qkv_gemm_kernel() {
    extern __shared__ __align__(1024) char smem[];
    const uint32_t sbase = smem_to_u32(smem);
    const int tid  = threadIdx.x;
    const int wid  = tid >> 5;
    const int lane = tid & 31;
    const int n0 = blockIdx.x * TN;       // N fastest (L2 reuse of A across row)
    const int m0 = blockIdx.y * TM;
    const int warp_m = (wid & 3) * 32;    // 4 warps along M
    const int warp_n = (wid >> 2) * 64;   // 2 warps along N

    auto load_chunk = [&](int c) {
        const uint32_t stb = sbase + (uint32_t)(c % STAGES) * 32768u;
        const size_t k0 = (size_t)c * KC;
        #pragma unroll
        for (int l = 0; l < 8; l++) {
            int i   = tid + l * 256;      // 0..2047
            int arr = i >> 10;            // 0 = A, 1 = B
            int w   = i & 1023;
            int r   = w >> 3;             // row 0..127
            int j   = w & 7;              // 16B piece
            uint32_t dst = stb + (uint32_t)arr * 16384u
                         + sw128((uint32_t)(r * 128 + j * 16));
            const __half* src = arr
                ? g_w + ((size_t)(n0 + r) * K_ALL + k0 + j * 8)
                : g_x + ((size_t)(m0 + r) * K_ALL + k0 + j * 8);
            CP_ASYNC16(dst, src);
        }
        CP_ASYNC_COMMIT();
    };

    load_chunk(0);
    load_chunk(1);

    float acc[2][8][4];
    #pragma unroll
    for (int i = 0; i < 2; i++)
        #pragma unroll
        for (int j = 0; j < 8; j++)
            #pragma unroll
            for (int e = 0; e < 4; e++) acc[i][j][e] = 0.f;

    const int colb_lane = ((lane >> 4) << 4);
    const int row_lane  = (lane & 15);

    for (int c = 0; c < NCHUNK; c++) {
        if (c == NCHUNK - 1) asm volatile("cp.async.wait_group 0;\n" ::: "memory");
        else                 asm volatile("cp.async.wait_group 1;\n" ::: "memory");
        __syncthreads();
        // Buffer (c+2)%3 was consumed as chunk c-1 by all warps (the barrier
        // above orders that), so refill it now.
        if (c + 2 < NCHUNK) load_chunk(c + 2);

        const uint32_t sA = sbase + (uint32_t)(c % STAGES) * 32768u;
        const uint32_t sB = sA + 16384u;
        #pragma unroll
        for (int ks = 0; ks < 4; ks++) {
            const int colb = ks * 32 + colb_lane;
            uint32_t b[4][4], a[2][4];
            #pragma unroll
            for (int t = 0; t < 4; t++) {
                uint32_t off = (uint32_t)((warp_n + 16 * t + row_lane) * 128 + colb);
                ldmatrix_x4(b[t], sB + sw128(off));
            }
            #pragma unroll
            for (int i = 0; i < 2; i++) {
                uint32_t off = (uint32_t)((warp_m + 16 * i + row_lane) * 128 + colb);
                ldmatrix_x4(a[i], sA + sw128(off));
            }
            #pragma unroll
            for (int i = 0; i < 2; i++)
                #pragma unroll
                for (int t = 0; t < 4; t++) {
                    mma_f16(acc[i][2 * t],     a[i], b[t][0], b[t][2]);
                    mma_f16(acc[i][2 * t + 1], a[i], b[t][1], b[t][3]);
                }
        }
    }

    // Epilogue: bias + relu, direct to g_qkv.
    const int rr = lane >> 2;
    const int cc = (lane & 3) * 2;
    #pragma unroll
    for (int i = 0; i < 2; i++) {
        const int gm = m0 + warp_m + 16 * i + rr;
        #pragma unroll
        for (int j = 0; j < 8; j++) {
            const int gn = n0 + warp_n + 8 * j + cc;
            const float b0 = g_bias[gn], b1 = g_bias[gn + 1];
            float2 o0, o1;
            o0.x = fmaxf(acc[i][j][0] + b0, 0.f);
            o0.y = fmaxf(acc[i][j][1] + b1, 0.f);
            o1.x = fmaxf(acc[i][j][2] + b0, 0.f);
            o1.y = fmaxf(acc[i][j][3] + b1, 0.f);
            *(float2*)(g_qkv + (size_t)gm * N_ALL + gn)       = o0;
            *(float2*)(g_qkv + (size_t)(gm + 8) * N_ALL + gn) = o1;
        }
    }
}

// ====================== attention + residual + LN =======================
// One CTA (256 threads) per batch row b. k (then v) tile in smem; q, x
// streamed from global. Register blocking (groups of 5 t) so the smem tile
// is read 2x per phase instead of 10x (cuts LDS/L1 traffic ~4x).
__global__ void __launch_bounds__(256) attn_kernel(
    const float* __restrict__ x_in, const float* __restrict__ pe,
    const float* __restrict__ gamma, const float* __restrict__ beta,
    float* __restrict__ out_x, float* __restrict__ out_attn, int write_attn) {
    extern __shared__ __align__(16) char smem_raw[];
    float* kv     = (float*)smem_raw;    // 10 x 1024
    float* logits = kv + 10240;          // 100 (pad 104)
    float* red    = logits + 104;        // 400: 8 warps x 50 partials

    const int tid = threadIdx.x, wid = tid >> 5, lid = tid & 31;
    const size_t b = blockIdx.x;
    const float* qkv_b = g_qkv + b * (size_t)TT * N_ALL;
    const int d0 = tid * 4;

    // Stage k
    for (int i = tid; i < 2560; i += 256) {
        int t = i >> 8, c = (i & 255) * 4;
        *(float4*)(kv + t * DD + c) =
            *(const float4*)(qkv_b + (size_t)t * N_ALL + DD + c);
    }
    __syncthreads();

    // Phase 1: logits[t][s] = (q[t].k[s]) / sqrt(D); q in registers, 5 t at a time.
    const float scale = rsqrtf((float)DD);
    #pragma unroll
    for (int g = 0; g < 2; g++) {
        float4 q4[5];
        #pragma unroll
        for (int j = 0; j < 5; j++)
            q4[j] = *(const float4*)(qkv_b + (size_t)(g * 5 + j) * N_ALL + d0);
        float part[5][TT];
        #pragma unroll
        for (int j = 0; j < 5; j++)
            #pragma unroll
            for (int s = 0; s < TT; s++) part[j][s] = 0.f;
        #pragma unroll
        for (int s = 0; s < TT; s++) {
            float4 k4 = *(const float4*)(kv + s * DD + d0);
            #pragma unroll
            for (int j = 0; j < 5; j++)
                part[j][s] += q4[j].x * k4.x + q4[j].y * k4.y
                            + q4[j].z * k4.z + q4[j].w * k4.w;
        }
        #pragma unroll
        for (int o = 16; o; o >>= 1)
            #pragma unroll
            for (int j = 0; j < 5; j++)
                #pragma unroll
                for (int s = 0; s < TT; s++)
                    part[j][s] += __shfl_xor_sync(0xFFFFFFFFu, part[j][s], o);
        if (lid == 0)
            #pragma unroll
            for (int j = 0; j < 5; j++)
                #pragma unroll
                for (int s = 0; s < TT; s++)
                    red[wid * 50 + j * TT + s] = part[j][s];
        __syncthreads();
        if (tid < 50) {
            float a2 = 0.f;
            #pragma unroll
            for (int w = 0; w < 8; w++) a2 += red[w * 50 + tid];
            int j = tid / TT, s = tid % TT;
            logits[(g * 5 + j) * TT + s] = a2 * scale;
        }
        __syncthreads();
    }

    // Phase 2: softmax rows (threads 0..9), write attn output.
    if (tid < TT) {
        float m = -1e30f;
        #pragma unroll
        for (int s = 0; s < TT; s++) m = fmaxf(m, logits[tid * TT + s]);
        float e[TT], sum = 0.f;
        #pragma unroll
        for (int s = 0; s < TT; s++) { e[s] = expf(logits[tid * TT + s] - m); sum += e[s]; }
        float inv = 1.f / sum;
        #pragma unroll
        for (int s = 0; s < TT; s++) {
            float a = e[s] * inv;
            logits[tid * TT + s] = a;
            if (write_attn) out_attn[(b * TT + tid) * TT + s] = a;
        }
    }
    __syncthreads();

    // Stage v (overwrite kv)
    for (int i = tid; i < 2560; i += 256) {
        int t = i >> 8, c = (i & 255) * 4;
        *(float4*)(kv + t * DD + c) =
            *(const float4*)(qkv_b + (size_t)t * N_ALL + 2 * DD + c);
    }
    __syncthreads();

    // Phase 3: out = attn @ v (register-blocked, one v pass per 5-group);
    // residual (x streamed); LayerNorm; coalesced store.
    const float4 g4  = *(const float4*)(gamma + d0);
    const float4 be4 = *(const float4*)(beta + d0);
    #pragma unroll
    for (int g = 0; g < 2; g++) {
        float4 o[5];
        #pragma unroll
        for (int j = 0; j < 5; j++) o[j] = make_float4(0.f, 0.f, 0.f, 0.f);
        #pragma unroll
        for (int s = 0; s < TT; s++) {
            float4 v4 = *(const float4*)(kv + s * DD + d0);
            #pragma unroll
            for (int j = 0; j < 5; j++) {
                float a = logits[(g * 5 + j) * TT + s];
                o[j].x += a * v4.x; o[j].y += a * v4.y;
                o[j].z += a * v4.z; o[j].w += a * v4.w;
            }
        }
        #pragma unroll
        for (int j = 0; j < 5; j++) {
            const int t = g * 5 + j;
            float4 xv = *(const float4*)(x_in + (b * TT + t) * (size_t)DD + d0);
            float4 pv = *(const float4*)(pe + (size_t)t * DD + d0);
            float4 v;
            v.x = xv.x + pv.x + o[j].x;
            v.y = xv.y + pv.y + o[j].y;
            v.z = xv.z + pv.z + o[j].z;
            v.w = xv.w + pv.w + o[j].w;
            float s1 = v.x + v.y + v.z + v.w;
            float s2 = v.x * v.x + v.y * v.y + v.z * v.z + v.w * v.w;
            #pragma unroll
            for (int of = 16; of; of >>= 1) {
                s1 += __shfl_xor_sync(0xFFFFFFFFu, s1, of);
                s2 += __shfl_xor_sync(0xFFFFFFFFu, s2, of);
            }
            if (lid == 0) { red[wid] = s1; red[8 + wid] = s2; }
            __syncthreads();
            if (tid == 0) {
                float ts1 = 0.f, ts2 = 0.f;
                #pragma unroll
                for (int w = 0; w < 8; w++) { ts1 += red[w]; ts2 += red[8 + w]; }
                float mu  = ts1 * (1.f / DD);
                float var = ts2 * (1.f / DD) - mu * mu;
                red[16] = mu;
                red[17] = rsqrtf(var + EPSV);
            }
            __syncthreads();
            float mu = red[16], rstd = red[17];
            float4 r;
            r.x = (v.x - mu) * rstd * g4.x + be4.x;
            r.y = (v.y - mu) * rstd * g4.y + be4.y;
            r.z = (v.z - mu) * rstd * g4.z + be4.z;
            r.w = (v.w - mu) * rstd * g4.w + be4.w;
            *(float4*)(out_x + (b * TT + t) * (size_t)DD + d0) = r;
            __syncthreads();  // protect red[] reuse
        }
    }
}

// ============================ launch ====================================
extern "C" void kernel_launch(void* const* d_in, const int* in_sizes, int n_in,
                              void* d_out, int out_size) {
    const float* x     = (const float*)d_in[0];
    const float* pe    = (const float*)d_in[1];
    const float* Wq    = (const float*)d_in[2];
    const float* bq    = (const float*)d_in[3];
    const float* Wk    = (const float*)d_in[4];
    const float* bk    = (const float*)d_in[5];
    const float* Wv    = (const float*)d_in[6];
    const float* bv    = (const float*)d_in[7];
    const float* gamma = (const float*)d_in[8];
    const float* beta  = (const float*)d_in[9];
    float* out = (float*)d_out;

    (void)in_sizes; (void)n_in;

    cudaFuncSetAttribute(qkv_gemm_kernel,
                         cudaFuncAttributeMaxDynamicSharedMemorySize, 98304);
    cudaFuncSetAttribute(attn_kernel,
                         cudaFuncAttributeMaxDynamicSharedMemorySize, 43008);

    // 1) x+pe -> fp16; W -> fp16
    prep_x_kernel<<<81920, 256>>>(x, pe);
    prep_w_kernel<<<3072, 256>>>(Wq, Wk, Wv, bq, bk, bv);

    // 2) qkv = relu(x @ [Wq;Wk;Wv]^T + b), single-term fp16 mma.sync
    dim3 ggrid(N_ALL / TN, M_ALL / TM);   // (24, 640) — N fastest for L2 reuse
    qkv_gemm_kernel<<<ggrid, 256, 98304>>>();

    // 3) attention + softmax + residual + LN (+ attn matrix output)
    long long need = (long long)M_ALL * DD + (long long)BB * TT * TT;
    int write_attn = ((long long)out_size >= need) ? 1 : 0;
    attn_kernel<<<BB, 256, 43008>>>(x, pe, gamma, beta,
                                    out, out + (size_t)M_ALL * DD, write_attn);
}